// round 5
// baseline (speedup 1.0000x reference)
#include <cuda_runtime.h>
#include <cuda_fp16.h>
#include <cstdint>

#define N_TOK 8192
#define DDIM  2048
#define MDIM  512
#define NEXP  4
#define NP_MAX (N_TOK + NEXP*128)   // 8704 worst-case padded slots
#define NTILES (NP_MAX/128)         // 68

// ---------------- scratch (device globals; no allocation allowed) ----------------
__device__ int d_padoff[NEXP+1];
__device__ int d_tok[NP_MAX];
__device__ __half d_x16[(size_t)NP_MAX*DDIM];        // gathered, expert-sorted x (fp16)
__device__ __half d_h16[(size_t)NP_MAX*MDIM];        // hidden activations (fp16)
__device__ __half d_w1h[(size_t)NEXP*MDIM*DDIM];     // W1 fp16
__device__ __half d_w2h[(size_t)NEXP*DDIM*MDIM];     // W2 fp16

// ---------------- fused routing kernel (single block, 1024 threads) ----------------
// Replaces init/count/scan/fill/perm (5 launches -> 1). Ballot-aggregated counting
// and ranked scatter: 4 smem atomics per warp-iteration instead of 32.
__global__ void k_route(const void* __restrict__ dom) {
    __shared__ int s_cnt[NEXP], s_cur[NEXP], s_off[NEXP+1];
    __shared__ int s_any;
    const int tid = threadIdx.x, lane = tid & 31;

    if (tid == 0) s_any = 0;
    if (tid < NEXP) { s_cnt[tid] = 0; s_cur[tid] = 0; }
    __syncthreads();

    // dtype detect: int64 => odd 32-bit words of the first N_TOK words are all 0
    const unsigned* w = (const unsigned*)dom;
    int any = 0;
    for (int i = 1 + 2*tid; i < N_TOK; i += 2048)
        if (w[i] != 0) any = 1;
    if (any) s_any = 1;              // benign race
    __syncthreads();
    const int is64 = (s_any == 0);

    // pass 1: count per expert (warp-aggregated)
    for (int i = tid; i < N_TOK; i += 1024) {
        int e = is64 ? (int)((const long long*)dom)[i] : ((const int*)dom)[i];
        #pragma unroll
        for (int ee = 0; ee < NEXP; ee++) {
            unsigned b = __ballot_sync(0xffffffffu, e == ee);
            if (lane == __ffs(b) - 1) atomicAdd(&s_cnt[ee], __popc(b));
        }
    }
    // fill pad slots with -1 while counts settle
    __syncthreads();
    if (tid == 0) {
        int off = 0;
        s_off[0] = 0; d_padoff[0] = 0;
        #pragma unroll
        for (int e = 0; e < NEXP; e++) {
            off += (s_cnt[e] + 127) & ~127;
            s_off[e+1] = off; d_padoff[e+1] = off;
        }
    }
    for (int i = tid; i < NP_MAX; i += 1024) d_tok[i] = -1;
    __syncthreads();

    // pass 2: ranked scatter (warp-aggregated cursor bump)
    for (int i = tid; i < N_TOK; i += 1024) {
        int e = is64 ? (int)((const long long*)dom)[i] : ((const int*)dom)[i];
        #pragma unroll
        for (int ee = 0; ee < NEXP; ee++) {
            unsigned b = __ballot_sync(0xffffffffu, e == ee);
            if (e == ee) {
                int leader = __ffs(b) - 1;
                int base = 0;
                if (lane == leader) base = atomicAdd(&s_cur[ee], __popc(b));
                base = __shfl_sync(b, base, leader);
                int rank = __popc(b & ((1u << lane) - 1));
                d_tok[s_off[ee] + base + rank] = i;
            }
        }
    }
}

// ---------------- fused convert (W1,W2 -> fp16) + gather (x -> sorted fp16) ----------------
#define CONV_QUADS (NEXP*MDIM*DDIM/4)        // 1048576
#define CONV_BLOCKS (CONV_QUADS/256)         // 4096
#define GATH_QUADS ((size_t)NP_MAX*DDIM/4)   // 4456448
#define GATH_BLOCKS (GATH_QUADS/256)         // 17408

__global__ void k_prep(const float* __restrict__ W1, const float* __restrict__ W2,
                       const float* __restrict__ x) {
    if (blockIdx.x < CONV_BLOCKS) {
        size_t q = (size_t)blockIdx.x * 256 + threadIdx.x;
        size_t i = q * 4;
        float4 a = *(const float4*)(W1 + i);
        float4 b = *(const float4*)(W2 + i);
        *(__half2*)(d_w1h + i)     = __floats2half2_rn(a.x, a.y);
        *(__half2*)(d_w1h + i + 2) = __floats2half2_rn(a.z, a.w);
        *(__half2*)(d_w2h + i)     = __floats2half2_rn(b.x, b.y);
        *(__half2*)(d_w2h + i + 2) = __floats2half2_rn(b.z, b.w);
    } else {
        size_t q = (size_t)(blockIdx.x - CONV_BLOCKS) * 256 + threadIdx.x;
        int slot = (int)(q >> 9);               // DDIM/4 = 512 quads per row
        int off  = ((int)q & 511) * 4;
        if (slot >= d_padoff[NEXP]) return;
        int tok = d_tok[slot];
        __half2 h0, h1;
        if (tok >= 0) {
            float4 v = *(const float4*)(x + (size_t)tok * DDIM + off);
            h0 = __floats2half2_rn(v.x, v.y);
            h1 = __floats2half2_rn(v.z, v.w);
        } else {
            h0 = __half2{__ushort_as_half(0), __ushort_as_half(0)};
            h1 = h0;
        }
        size_t o = (size_t)slot * DDIM + off;
        *(__half2*)(d_x16 + o) = h0;
        *(__half2*)(d_x16 + o + 2) = h1;
    }
}

// ---------------- HMMA (mma.sync) GEMM: ldmatrix + SW128, single-sync 4-stage pipeline ----
// C[slot, n] = sum_k A[slot,k] * B[e][n][k]
// PHASE0: A=d_x16 (K=2048), B=W1, NOUT=512  -> relu(acc+b1) -> d_h16 (fp16)
// PHASE1: A=d_h16 (K=512),  B=W2, NOUT=2048 -> x + acc + b2 -> out (scatter fp32)

__device__ __forceinline__ void mma16816(float* c, const unsigned* a, const unsigned* b) {
    asm volatile(
        "mma.sync.aligned.m16n8k16.row.col.f32.f16.f16.f32 "
        "{%0,%1,%2,%3}, {%4,%5,%6,%7}, {%8,%9}, {%0,%1,%2,%3};\n"
        : "+f"(c[0]), "+f"(c[1]), "+f"(c[2]), "+f"(c[3])
        : "r"(a[0]), "r"(a[1]), "r"(a[2]), "r"(a[3]), "r"(b[0]), "r"(b[1]));
}
__device__ __forceinline__ void ldsm4(unsigned* r, unsigned addr) {
    asm volatile("ldmatrix.sync.aligned.m8n8.x4.shared.b16 {%0,%1,%2,%3}, [%4];"
        : "=r"(r[0]), "=r"(r[1]), "=r"(r[2]), "=r"(r[3]) : "r"(addr));
}
__device__ __forceinline__ uint32_t smem_u32(const void* p) {
    uint32_t a;
    asm("{ .reg .u64 t; cvta.to.shared.u64 t, %1; cvt.u32.u64 %0, t; }" : "=r"(a) : "l"(p));
    return a;
}

#define GTM 128
#define GTN 128
#define GKC 64                         // halfs per K-chunk (128B rows)
#define GSTAGES 4
#define STAGE_BYTES (GTM*128)          // 16 KB
#define GSMEM_TOTAL (GSTAGES*2*STAGE_BYTES)   // 128 KB

__device__ __forceinline__ uint32_t swz(int row, int unit) {
    return (uint32_t)(row * 128 + ((unit ^ (row & 7)) * 16));
}

template<int PHASE, int K, int NOUT>
__global__ __launch_bounds__(256)
void gemm_hmma(const float* __restrict__ bias,
               const float* __restrict__ xres,
               float* __restrict__ outf)
{
    constexpr int NCH = K / GKC;

    extern __shared__ char smem[];
    const uint32_t sb = smem_u32(smem);

    const int tid = threadIdx.x, warp = tid >> 5, lane = tid & 31;
    const int wm = warp >> 1, wn = warp & 1;   // 4 warps in M, 2 in N; warp tile 32x64

    const int mbase = blockIdx.x * GTM;
    if (mbase >= d_padoff[NEXP]) return;
    int e = 0;
    while (e < NEXP-1 && mbase >= d_padoff[e+1]) e++;
    const int nbase = blockIdx.y * GTN;

    const __half* __restrict__ A = (PHASE == 0) ? d_x16 : d_h16;
    const __half* __restrict__ B = (PHASE == 0) ? d_w1h : d_w2h;
    const __half* Ab = A + (size_t)mbase * K;
    const __half* Bb = B + ((size_t)e * NOUT + nbase) * K;

    auto load_chunk = [&](int i) {
        const int s = i % GSTAGES;
        const int k0 = i * GKC;
        const uint32_t abase = sb + s * STAGE_BYTES;
        const uint32_t bbase = sb + (GSTAGES + s) * STAGE_BYTES;
        #pragma unroll
        for (int it = 0; it < 4; it++) {
            int c = tid + it * 256;
            int row = c >> 3, u = c & 7;
            const void* srcA = Ab + (size_t)row * K + k0 + u * 8;
            const void* srcB = Bb + (size_t)row * K + k0 + u * 8;
            uint32_t o = swz(row, u);
            asm volatile("cp.async.cg.shared.global [%0], [%1], 16;\n" :: "r"(abase + o), "l"(srcA) : "memory");
            asm volatile("cp.async.cg.shared.global [%0], [%1], 16;\n" :: "r"(bbase + o), "l"(srcB) : "memory");
        }
    };

    float acc[2][8][4];
    #pragma unroll
    for (int i = 0; i < 2; i++)
        #pragma unroll
        for (int j = 0; j < 8; j++)
            #pragma unroll
            for (int l = 0; l < 4; l++) acc[i][j][l] = 0.f;

    // prologue: S-1 chunks in flight
    #pragma unroll
    for (int i = 0; i < GSTAGES - 1; i++) {
        load_chunk(i);
        asm volatile("cp.async.commit_group;\n" ::: "memory");
    }

    // ldmatrix lane address components (within a stage)
    const int aRowLo = wm * 32 + ((lane >> 3) & 1) * 8 + (lane & 7);  // + mi*16
    const int aUnitLo = (lane >> 4);                                   // + s*2
    const int bRowLo = wn * 64 + ((lane >> 4) << 3) + (lane & 7);      // + nf*16
    const int bUnitLo = ((lane >> 3) & 1);                             // + s*2

    #pragma unroll 1
    for (int i = 0; i < NCH; i++) {
        const int st = i % GSTAGES;
        asm volatile("cp.async.wait_group %0;\n" :: "n"(GSTAGES - 2) : "memory");
        __syncthreads();   // chunk i resident; every warp done computing chunk i-1

        // prefetch into the stage retired last iteration (safe under the sync above)
        if (i + GSTAGES - 1 < NCH) load_chunk(i + GSTAGES - 1);
        asm volatile("cp.async.commit_group;\n" ::: "memory");

        const uint32_t abase = sb + st * STAGE_BYTES;
        const uint32_t bbase = sb + (GSTAGES + st) * STAGE_BYTES;
        #pragma unroll
        for (int s = 0; s < 4; s++) {              // 4 k-steps of 16 per chunk
            unsigned a[2][4], b[4][4];
            #pragma unroll
            for (int mi = 0; mi < 2; mi++)
                ldsm4(a[mi], abase + swz(aRowLo + mi * 16, s * 2 + aUnitLo));
            #pragma unroll
            for (int nf = 0; nf < 4; nf++)
                ldsm4(b[nf], bbase + swz(bRowLo + nf * 16, s * 2 + bUnitLo));
            #pragma unroll
            for (int mi = 0; mi < 2; mi++)
                #pragma unroll
                for (int nf = 0; nf < 4; nf++) {
                    mma16816(acc[mi][nf*2+0], a[mi], &b[nf][0]);
                    mma16816(acc[mi][nf*2+1], a[mi], &b[nf][2]);
                }
        }
    }

    // ---------------- epilogue ----------------
    const int g = lane >> 2, q = lane & 3;
    #pragma unroll
    for (int mi = 0; mi < 2; mi++) {
        #pragma unroll
        for (int hf = 0; hf < 2; hf++) {
            const int slot = mbase + wm * 32 + mi * 16 + hf * 8 + g;
            if (PHASE == 1) {
                const int tok = d_tok[slot];
                if (tok < 0) continue;
                #pragma unroll
                for (int ni = 0; ni < 8; ni++) {
                    const int col = nbase + wn * 64 + ni * 8 + q * 2;
                    const size_t o = (size_t)tok * NOUT + col;
                    float2 xr = *(const float2*)(xres + o);
                    float b0 = bias[e * NOUT + col], b1 = bias[e * NOUT + col + 1];
                    float2 r;
                    r.x = acc[mi][ni][hf*2+0] + b0 + xr.x;
                    r.y = acc[mi][ni][hf*2+1] + b1 + xr.y;
                    *(float2*)(outf + o) = r;
                }
            } else {
                #pragma unroll
                for (int ni = 0; ni < 8; ni++) {
                    const int col = nbase + wn * 64 + ni * 8 + q * 2;
                    float v0 = acc[mi][ni][hf*2+0] + bias[e * NOUT + col];
                    float v1 = acc[mi][ni][hf*2+1] + bias[e * NOUT + col + 1];
                    *(__half2*)(d_h16 + (size_t)slot * NOUT + col) =
                        __floats2half2_rn(fmaxf(v0, 0.f), fmaxf(v1, 0.f));
                }
            }
        }
    }
}

// ---------------- launch (4 kernels total) ----------------
extern "C" void kernel_launch(void* const* d_in, const int* in_sizes, int n_in,
                              void* d_out, int out_size) {
    const float* x   = (const float*)d_in[0];
    const void*  dom = d_in[1];
    const float* W1  = (const float*)d_in[2];
    const float* b1  = (const float*)d_in[3];
    const float* W2  = (const float*)d_in[4];
    const float* b2  = (const float*)d_in[5];
    float* out = (float*)d_out;
    (void)in_sizes; (void)n_in; (void)out_size;

    cudaFuncSetAttribute(gemm_hmma<0, DDIM, MDIM>,
                         cudaFuncAttributeMaxDynamicSharedMemorySize, GSMEM_TOTAL);
    cudaFuncSetAttribute(gemm_hmma<1, MDIM, DDIM>,
                         cudaFuncAttributeMaxDynamicSharedMemorySize, GSMEM_TOTAL);

    k_route<<<1, 1024>>>(dom);
    k_prep<<<CONV_BLOCKS + (int)GATH_BLOCKS, 256>>>(W1, W2, x);
    gemm_hmma<0, DDIM, MDIM><<<dim3(NTILES, MDIM / GTN), 256, GSMEM_TOTAL>>>(b1, nullptr, nullptr);
    gemm_hmma<1, MDIM, DDIM><<<dim3(NTILES, DDIM / GTN), 256, GSMEM_TOTAL>>>(b2, x, out);
}